// round 1
// baseline (speedup 1.0000x reference)
#include <cuda_runtime.h>
#include <math.h>

// Problem constants
#define B_   8
#define T_   1048576
#define E_   8
#define C_   128
#define KW_  512
#define S_   512
#define L_   2048          // (T-K)/S + 1
#define Mtot 16384         // B*L
#define KK   4096          // K*E
#define NN   256           // 2*C (both convs fused)

// GEMM tiling
#define MT       64
#define KC       16
#define NTHREADS 256

// Scratch: repacked weights Wt[(k*E+e)*NN + n], n<128 -> W1 channel, n>=128 -> W2 channel
__device__ float g_Wt[KK * NN];   // 4 MB

__global__ void prep_weights(const float* __restrict__ W1, const float* __restrict__ W2) {
    int idx = blockIdx.x * blockDim.x + threadIdx.x;   // over C*E*K = 524288
    if (idx >= C_ * E_ * KW_) return;
    int k = idx % KW_;
    int e = (idx / KW_) % E_;
    int c = idx / (KW_ * E_);
    int kk = k * E_ + e;
    g_Wt[(size_t)kk * NN + c]       = W1[idx];
    g_Wt[(size_t)kk * NN + C_ + c]  = W2[idx];
}

__global__ void init_out(float* out) {
    int i = blockIdx.x * blockDim.x + threadIdx.x;
    if (i < B_ * C_) out[i] = -INFINITY;
}

__device__ __forceinline__ void atomicMaxFloat(float* addr, float val) {
    if (val >= 0.0f) {
        atomicMax((int*)addr, __float_as_int(val));
    } else {
        atomicMin((unsigned int*)addr, __float_as_uint(val));
    }
}

__global__ __launch_bounds__(NTHREADS, 2)
void gemm_gate_max(const float* __restrict__ Z,
                   const float* __restrict__ b1,
                   const float* __restrict__ b2,
                   float* __restrict__ out) {
    __shared__ float As[2][KC][MT + 4];   // padded to kill STS conflicts
    __shared__ float Bs[2][KC][NN];
    __shared__ float red[8][32][4];

    const int tid = threadIdx.x;
    const int tx  = tid & 31;   // 32 column groups (4 cols each, x2 halves)
    const int ty  = tid >> 5;   // 8 row groups (8 rows each)
    const int m_base = blockIdx.x * MT;

    // ---- global load mapping ----
    // A tile: 64 rows x 16 k = 256 float4 -> 1 per thread
    const int a_row = tid >> 2;            // 0..63
    const int a_k4  = (tid & 3) * 4;       // 0,4,8,12
    const float* Aptr = Z + (size_t)(m_base + a_row) * KK + a_k4;
    // B tile: 16 x 256 = 1024 float4 -> 4 per thread (rows b_row+4s)
    const int b_row = tid >> 6;            // 0..3
    const int b_col = (tid & 63) * 4;      // 0..252

    float acc[8][8];
    #pragma unroll
    for (int i = 0; i < 8; i++)
        #pragma unroll
        for (int j = 0; j < 8; j++) acc[i][j] = 0.0f;

    // ---- prologue: stage 0 ----
    float4 av = *(const float4*)Aptr;
    float4 bv[4];
    #pragma unroll
    for (int s = 0; s < 4; s++)
        bv[s] = *(const float4*)&g_Wt[(size_t)(b_row + 4 * s) * NN + b_col];

    As[0][a_k4 + 0][a_row] = av.x;
    As[0][a_k4 + 1][a_row] = av.y;
    As[0][a_k4 + 2][a_row] = av.z;
    As[0][a_k4 + 3][a_row] = av.w;
    #pragma unroll
    for (int s = 0; s < 4; s++)
        *(float4*)&Bs[0][b_row + 4 * s][b_col] = bv[s];
    __syncthreads();

    const int NITER = KK / KC;   // 256
    for (int it = 0; it < NITER; ++it) {
        const int cur = it & 1;
        const int nxt = cur ^ 1;

        if (it + 1 < NITER) {
            const int kc = (it + 1) * KC;
            av = *(const float4*)(Aptr + kc);
            #pragma unroll
            for (int s = 0; s < 4; s++)
                bv[s] = *(const float4*)&g_Wt[(size_t)(kc + b_row + 4 * s) * NN + b_col];
        }

        #pragma unroll
        for (int k = 0; k < KC; k++) {
            float4 a0 = *(const float4*)&As[cur][k][ty * 8];
            float4 a1 = *(const float4*)&As[cur][k][ty * 8 + 4];
            float4 p0 = *(const float4*)&Bs[cur][k][tx * 4];
            float4 p1 = *(const float4*)&Bs[cur][k][C_ + tx * 4];
            float a[8] = {a0.x, a0.y, a0.z, a0.w, a1.x, a1.y, a1.z, a1.w};
            float b[8] = {p0.x, p0.y, p0.z, p0.w, p1.x, p1.y, p1.z, p1.w};
            #pragma unroll
            for (int i = 0; i < 8; i++)
                #pragma unroll
                for (int j = 0; j < 8; j++)
                    acc[i][j] = fmaf(a[i], b[j], acc[i][j]);
        }

        if (it + 1 < NITER) {
            As[nxt][a_k4 + 0][a_row] = av.x;
            As[nxt][a_k4 + 1][a_row] = av.y;
            As[nxt][a_k4 + 2][a_row] = av.z;
            As[nxt][a_k4 + 3][a_row] = av.w;
            #pragma unroll
            for (int s = 0; s < 4; s++)
                *(float4*)&Bs[nxt][b_row + 4 * s][b_col] = bv[s];
        }
        __syncthreads();
    }

    // ---- epilogue: bias + gate + max over rows ----
    const int c0 = tx * 4;
    float bias1[4], bias2[4];
    #pragma unroll
    for (int q = 0; q < 4; q++) {
        bias1[q] = b1[c0 + q];
        bias2[q] = b2[c0 + q];
    }

    float gmax[4] = {-INFINITY, -INFINITY, -INFINITY, -INFINITY};
    #pragma unroll
    for (int i = 0; i < 8; i++) {
        #pragma unroll
        for (int q = 0; q < 4; q++) {
            float v1 = acc[i][q]     + bias1[q];
            float v2 = acc[i][4 + q] + bias2[q];
            float g  = v1 / (1.0f + expf(-v2));
            gmax[q] = fmaxf(gmax[q], g);
        }
    }

    #pragma unroll
    for (int q = 0; q < 4; q++) red[ty][tx][q] = gmax[q];
    __syncthreads();

    if (ty == 0) {
        const int bidx = m_base / L_;
        #pragma unroll
        for (int q = 0; q < 4; q++) {
            float v = red[0][tx][q];
            #pragma unroll
            for (int r = 1; r < 8; r++) v = fmaxf(v, red[r][tx][q]);
            atomicMaxFloat(&out[bidx * C_ + c0 + q], v);
        }
    }
}

extern "C" void kernel_launch(void* const* d_in, const int* in_sizes, int n_in,
                              void* d_out, int out_size) {
    const float* z  = (const float*)d_in[0];
    const float* W1 = (const float*)d_in[1];
    const float* b1 = (const float*)d_in[2];
    const float* W2 = (const float*)d_in[3];
    const float* b2 = (const float*)d_in[4];
    float* out = (float*)d_out;

    (void)in_sizes; (void)n_in; (void)out_size;

    prep_weights<<<(C_ * E_ * KW_ + 255) / 256, 256>>>(W1, W2);
    init_out<<<(B_ * C_ + 255) / 256, 256>>>(out);
    gemm_gate_max<<<Mtot / MT, NTHREADS>>>(z, b1, b2, out);
}

// round 3
// speedup vs baseline: 2.0693x; 2.0693x over previous
#include <cuda_runtime.h>
#include <cuda_bf16.h>
#include <math.h>
#include <stdint.h>

// ---------------- problem constants ----------------
#define B_   8
#define E_   8
#define C_   128
#define KW_  512
#define Mtot 16384          // B*L
#define KKd  4096           // KW*E
#define NNd  256            // 2*C

// ---------------- GEMM tiling ----------------
#define MT     128          // CTA M tile
#define NT     256          // CTA N tile (full N)
#define KC     32           // K chunk (bf16 elems)
#define NCHUNK (KKd / KC)   // 128
#define NTH    256          // 8 warps: 2(M) x 4(N), warp tile 64x64

// smem pitches/strides (bytes)
#define PITCH   80          // 40 bf16 per row (32 data + 8 pad) -> conflict-free ldmatrix
#define A_STG   (128 * PITCH)        // 10240 per stage
#define B_STG   (256 * PITCH)        // 20480 per stage
#define SM_AH   0
#define SM_AL   (SM_AH + 2 * A_STG)  // 20480
#define SM_BH   (SM_AL + 2 * A_STG)  // 40960
#define SM_BL   (SM_BH + 2 * B_STG)  // 81920
#define SM_PIPE (SM_BL + 2 * B_STG)  // 122880
// epilogue overlay (floats): tile [128][258] + partials [256]
#define EPITCH  258
#define SMEMSZ  (((128 * EPITCH + 256) * 4 > SM_PIPE) ? (128 * EPITCH + 256) * 4 : SM_PIPE)

// pre-split weights, [n][kk] K-major; n<128 -> W1, n>=128 -> W2
__device__ __nv_bfloat16 g_Bhi[(size_t)NNd * KKd];
__device__ __nv_bfloat16 g_Blo[(size_t)NNd * KKd];

// ---------------- helpers ----------------
__device__ __forceinline__ uint32_t smem_u32(const void* p) {
    uint32_t a;
    asm("{ .reg .u64 t; cvta.to.shared.u64 t, %1; cvt.u32.u64 %0, t; }" : "=r"(a) : "l"(p));
    return a;
}
__device__ __forceinline__ uint32_t pack_bf2(float x, float y) {
    __nv_bfloat162 t = __floats2bfloat162_rn(x, y);
    return *reinterpret_cast<uint32_t*>(&t);
}
__device__ __forceinline__ void ldmx4(uint32_t* r, uint32_t addr) {
    asm volatile("ldmatrix.sync.aligned.m8n8.x4.shared.b16 {%0,%1,%2,%3}, [%4];"
                 : "=r"(r[0]), "=r"(r[1]), "=r"(r[2]), "=r"(r[3]) : "r"(addr));
}
__device__ __forceinline__ void mma16816(float* d, const uint32_t* a, uint32_t b0, uint32_t b1) {
    asm volatile("mma.sync.aligned.m16n8k16.row.col.f32.bf16.bf16.f32 "
                 "{%0,%1,%2,%3}, {%4,%5,%6,%7}, {%8,%9}, {%0,%1,%2,%3};"
                 : "+f"(d[0]), "+f"(d[1]), "+f"(d[2]), "+f"(d[3])
                 : "r"(a[0]), "r"(a[1]), "r"(a[2]), "r"(a[3]), "r"(b0), "r"(b1));
}
__device__ __forceinline__ void sts64(uint32_t a, uint32_t x, uint32_t y) {
    asm volatile("st.shared.v2.b32 [%0], {%1,%2};" :: "r"(a), "r"(x), "r"(y) : "memory");
}
__device__ __forceinline__ void stsf2(uint32_t a, float x, float y) {
    asm volatile("st.shared.v2.f32 [%0], {%1,%2};" :: "r"(a), "f"(x), "f"(y) : "memory");
}
__device__ __forceinline__ void cpasync16(uint32_t dst, const void* src) {
    asm volatile("cp.async.cg.shared.global [%0], [%1], 16;" :: "r"(dst), "l"(src) : "memory");
}
__device__ __forceinline__ void cp_commit() { asm volatile("cp.async.commit_group;" ::: "memory"); }
__device__ __forceinline__ void cp_wait1() { asm volatile("cp.async.wait_group 1;" ::: "memory"); }
__device__ __forceinline__ void cp_wait0() { asm volatile("cp.async.wait_group 0;" ::: "memory"); }
__device__ __forceinline__ void atomicMaxFloat(float* addr, float val) {
    if (val >= 0.0f) atomicMax((int*)addr, __float_as_int(val));
    else             atomicMin((unsigned int*)addr, __float_as_uint(val));
}

// ---------------- prep: split weights into bf16 hi/lo, [n][kk] ----------------
__global__ void prep_weights(const float* __restrict__ W1, const float* __restrict__ W2) {
    int idx = blockIdx.x * blockDim.x + threadIdx.x;
    if (idx >= C_ * E_ * KW_) return;
    int k = idx % KW_;
    int e = (idx / KW_) % E_;
    int c = idx / (KW_ * E_);
    int kk = k * E_ + e;
    float w1 = W1[idx];
    __nv_bfloat16 h1 = __float2bfloat16(w1);
    g_Bhi[(size_t)c * KKd + kk] = h1;
    g_Blo[(size_t)c * KKd + kk] = __float2bfloat16(w1 - __bfloat162float(h1));
    float w2 = W2[idx];
    __nv_bfloat16 h2 = __float2bfloat16(w2);
    g_Bhi[(size_t)(C_ + c) * KKd + kk] = h2;
    g_Blo[(size_t)(C_ + c) * KKd + kk] = __float2bfloat16(w2 - __bfloat162float(h2));
}

__global__ void init_out(float* out) {
    int i = blockIdx.x * blockDim.x + threadIdx.x;
    if (i < B_ * C_) out[i] = -INFINITY;
}

// ---------------- main fused GEMM + gate + max ----------------
__global__ __launch_bounds__(NTH, 1)
void gemm_gate_max(const float* __restrict__ Z,
                   const float* __restrict__ b1,
                   const float* __restrict__ b2,
                   float* __restrict__ out) {
    extern __shared__ char smem[];
    const uint32_t sb = smem_u32(smem);
    const int tid  = threadIdx.x;
    const int wid  = tid >> 5;
    const int lane = tid & 31;
    const int wm   = wid & 1;        // M group (0..1), 64 rows
    const int wn   = wid >> 1;       // N group (0..3), 64 cols
    const int m_base = blockIdx.x * MT;

    // ldmatrix lane address component (within a [rows][PITCH] tile)
    const uint32_t fragBase = (uint32_t)((lane % 16) * PITCH + (lane / 16) * 16);
    const uint32_t wmOff = (uint32_t)(wm * 64 * PITCH);
    const uint32_t wnOff = (uint32_t)(wn * 64 * PITCH);

    // ---- A gmem/smem mapping: 4 float4 per thread per chunk ----
    const float* aSrc[4];
    uint32_t     aDst[4];   // byte offset within A stage
    {
#pragma unroll
        for (int q = 0; q < 4; q++) {
            int i   = tid + q * 256;       // 0..1023
            int row = i >> 3;              // 0..127
            int kw  = (i & 7) * 4;         // float index 0..28
            aSrc[q] = Z + (size_t)(m_base + row) * KKd + kw;
            aDst[q] = (uint32_t)(row * PITCH + kw * 2);
        }
    }
    // ---- B cp.async mapping: 4 granules (16B) per thread per (hi|lo) ----
    int      bN[4];
    uint32_t bDst[4];
    int      bKo[4];
    {
#pragma unroll
        for (int q = 0; q < 4; q++) {
            int g  = tid + q * 256;        // 0..1023
            bN[q]  = g >> 2;               // n: 0..255
            bKo[q] = (g & 3) * 8;          // bf16 offset in row
            bDst[q] = (uint32_t)(bN[q] * PITCH + bKo[q] * 2);
        }
    }

    float acc[4][8][4];
#pragma unroll
    for (int mi = 0; mi < 4; mi++)
#pragma unroll
        for (int ni = 0; ni < 8; ni++)
#pragma unroll
            for (int q = 0; q < 4; q++) acc[mi][ni][q] = 0.0f;

    float4 pA[4];

    // ---- prologue: chunk 0 ----
#pragma unroll
    for (int q = 0; q < 4; q++) pA[q] = *(const float4*)(aSrc[q]);
#pragma unroll
    for (int q = 0; q < 4; q++) {
        cpasync16(sb + SM_BH + bDst[q], g_Bhi + (size_t)bN[q] * KKd + bKo[q]);
        cpasync16(sb + SM_BL + bDst[q], g_Blo + (size_t)bN[q] * KKd + bKo[q]);
    }
    cp_commit();
#pragma unroll
    for (int q = 0; q < 4; q++) {
        float4 v = pA[q];
        float hx = __bfloat162float(__float2bfloat16(v.x));
        float hy = __bfloat162float(__float2bfloat16(v.y));
        float hz = __bfloat162float(__float2bfloat16(v.z));
        float hw = __bfloat162float(__float2bfloat16(v.w));
        sts64(sb + SM_AH + aDst[q], pack_bf2(hx, hy), pack_bf2(hz, hw));
        sts64(sb + SM_AL + aDst[q], pack_bf2(v.x - hx, v.y - hy), pack_bf2(v.z - hz, v.w - hw));
    }
#pragma unroll
    for (int q = 0; q < 4; q++) pA[q] = *(const float4*)(aSrc[q] + KC);

    for (int j = 0; j < NCHUNK; ++j) {
        const uint32_t cur = j & 1;
        const uint32_t nxt = cur ^ 1;

        __syncthreads();   // everyone done computing chunk j-1 -> safe to overwrite stage nxt

        if (j + 1 < NCHUNK) {
            const int ke = (j + 1) * KC;
#pragma unroll
            for (int q = 0; q < 4; q++) {
                cpasync16(sb + SM_BH + nxt * B_STG + bDst[q], g_Bhi + (size_t)bN[q] * KKd + ke + bKo[q]);
                cpasync16(sb + SM_BL + nxt * B_STG + bDst[q], g_Blo + (size_t)bN[q] * KKd + ke + bKo[q]);
            }
            cp_commit();
#pragma unroll
            for (int q = 0; q < 4; q++) {
                float4 v = pA[q];
                float hx = __bfloat162float(__float2bfloat16(v.x));
                float hy = __bfloat162float(__float2bfloat16(v.y));
                float hz = __bfloat162float(__float2bfloat16(v.z));
                float hw = __bfloat162float(__float2bfloat16(v.w));
                sts64(sb + SM_AH + nxt * A_STG + aDst[q], pack_bf2(hx, hy), pack_bf2(hz, hw));
                sts64(sb + SM_AL + nxt * A_STG + aDst[q],
                      pack_bf2(v.x - hx, v.y - hy), pack_bf2(v.z - hz, v.w - hw));
            }
            cp_wait1();
        } else {
            cp_wait0();
        }
        __syncthreads();   // stage cur fully visible

        if (j + 2 < NCHUNK) {
#pragma unroll
            for (int q = 0; q < 4; q++) pA[q] = *(const float4*)(aSrc[q] + (j + 2) * KC);
        }

        // ---- compute chunk j: 2 k16 slices x 3 precision passes ----
        const uint32_t sAh = sb + SM_AH + cur * A_STG;
        const uint32_t sAl = sb + SM_AL + cur * A_STG;
        const uint32_t sBh = sb + SM_BH + cur * B_STG;
        const uint32_t sBl = sb + SM_BL + cur * B_STG;

#pragma unroll
        for (int ks = 0; ks < 2; ks++) {
            const uint32_t ko = ks * 32;   // byte offset for k16 slice
            uint32_t af[4][4], bh[4][4], bl[4][4];
#pragma unroll
            for (int mi = 0; mi < 4; mi++)
                ldmx4(af[mi], sAh + wmOff + mi * (16 * PITCH) + ko + fragBase);
#pragma unroll
            for (int n2 = 0; n2 < 4; n2++)
                ldmx4(bh[n2], sBh + wnOff + n2 * (16 * PITCH) + ko + fragBase);
#pragma unroll
            for (int n2 = 0; n2 < 4; n2++)
                ldmx4(bl[n2], sBl + wnOff + n2 * (16 * PITCH) + ko + fragBase);
            // pass hh
#pragma unroll
            for (int mi = 0; mi < 4; mi++)
#pragma unroll
                for (int ni = 0; ni < 8; ni++)
                    mma16816(acc[mi][ni], af[mi], bh[ni >> 1][(ni & 1)], bh[ni >> 1][(ni & 1) + 2]);
            // pass hl
#pragma unroll
            for (int mi = 0; mi < 4; mi++)
#pragma unroll
                for (int ni = 0; ni < 8; ni++)
                    mma16816(acc[mi][ni], af[mi], bl[ni >> 1][(ni & 1)], bl[ni >> 1][(ni & 1) + 2]);
            // reload A = Al, pass lh
#pragma unroll
            for (int mi = 0; mi < 4; mi++)
                ldmx4(af[mi], sAl + wmOff + mi * (16 * PITCH) + ko + fragBase);
#pragma unroll
            for (int mi = 0; mi < 4; mi++)
#pragma unroll
                for (int ni = 0; ni < 8; ni++)
                    mma16816(acc[mi][ni], af[mi], bh[ni >> 1][(ni & 1)], bh[ni >> 1][(ni & 1) + 2]);
        }
    }

    // ---- epilogue: dump acc to smem tile [128][EPITCH] ----
    __syncthreads();
    {
        const int laneR = lane >> 2;
        const int laneC = (lane & 3) * 2;
#pragma unroll
        for (int mi = 0; mi < 4; mi++) {
#pragma unroll
            for (int ni = 0; ni < 8; ni++) {
                int r = wm * 64 + mi * 16 + laneR;
                int c = wn * 64 + ni * 8 + laneC;
                uint32_t a0 = sb + (uint32_t)(r * (EPITCH * 4) + c * 4);
                stsf2(a0,                     acc[mi][ni][0], acc[mi][ni][1]);
                stsf2(a0 + 8 * (EPITCH * 4),  acc[mi][ni][2], acc[mi][ni][3]);
            }
        }
    }
    __syncthreads();

    // ---- gate + max over the 128 rows ----
    {
        float* sE = (float*)smem;
        float* sP = sE + 128 * EPITCH;
        const int c   = tid & 127;
        const int seg = tid >> 7;
        const float bb1 = b1[c];
        const float bb2 = b2[c];
        float gm = -INFINITY;
        for (int m = seg * 64; m < seg * 64 + 64; ++m) {
            float v1 = sE[m * EPITCH + c] + bb1;
            float v2 = sE[m * EPITCH + 128 + c] + bb2;
            float g  = v1 / (1.0f + __expf(-v2));
            gm = fmaxf(gm, g);
        }
        sP[tid] = gm;
        __syncthreads();
        if (tid < 128) {
            float v = fmaxf(sP[tid], sP[tid + 128]);
            const int bidx = blockIdx.x >> 4;   // 16 CTAs per batch
            atomicMaxFloat(&out[bidx * C_ + c], v);
        }
    }
}

extern "C" void kernel_launch(void* const* d_in, const int* in_sizes, int n_in,
                              void* d_out, int out_size) {
    const float* z  = (const float*)d_in[0];
    const float* W1 = (const float*)d_in[1];
    const float* b1 = (const float*)d_in[2];
    const float* W2 = (const float*)d_in[3];
    const float* b2 = (const float*)d_in[4];
    float* out = (float*)d_out;
    (void)in_sizes; (void)n_in; (void)out_size;

    cudaFuncSetAttribute(gemm_gate_max, cudaFuncAttributeMaxDynamicSharedMemorySize, SMEMSZ);

    prep_weights<<<(C_ * E_ * KW_ + 255) / 256, 256>>>(W1, W2);
    init_out<<<(B_ * C_ + 255) / 256, 256>>>(out);
    gemm_gate_max<<<Mtot / MT, NTH, SMEMSZ>>>(z, b1, b2, out);
}

// round 4
// speedup vs baseline: 2.9784x; 1.4394x over previous
#include <cuda_runtime.h>
#include <cuda_fp16.h>
#include <math.h>
#include <stdint.h>

// ---------------- problem constants ----------------
#define B_   8
#define E_   8
#define C_   128
#define KW_  512
#define Mtot 16384          // B*L
#define KKd  4096           // KW*E
#define NNd  256            // 2*C

// ---------------- GEMM tiling ----------------
#define MT     128          // CTA M tile
#define KC     32           // K chunk (fp16 elems)
#define NCHUNK (KKd / KC)   // 128
#define NTH    256          // 8 warps: 2(M) x 4(N), warp tile 64x64

// smem pitches/strides (bytes)
#define PITCH   80          // 40 fp16 per row (32 data + 8 pad) -> conflict-free ldmatrix
#define A_STG   (128 * PITCH)        // 10240 per stage
#define B_STG   (256 * PITCH)        // 20480 per stage
#define SM_A    0
#define SM_BH   (2 * A_STG)          // 20480
#define SM_BL   (SM_BH + 2 * B_STG)  // 61440
#define SM_PIPE (SM_BL + 2 * B_STG)  // 102400
// epilogue overlay (floats): tile [128][258] + partials [256]
#define EPITCH  258
#define SMEMSZ  (((128 * EPITCH + 256) * 4 > SM_PIPE) ? (128 * EPITCH + 256) * 4 : SM_PIPE)

// pre-split weights, [n][kk] K-major; n<128 -> W1, n>=128 -> W2
__device__ __half g_Bhi[(size_t)NNd * KKd];
__device__ __half g_Blo[(size_t)NNd * KKd];

// ---------------- helpers ----------------
__device__ __forceinline__ uint32_t smem_u32(const void* p) {
    uint32_t a;
    asm("{ .reg .u64 t; cvta.to.shared.u64 t, %1; cvt.u32.u64 %0, t; }" : "=r"(a) : "l"(p));
    return a;
}
__device__ __forceinline__ uint32_t pack_h2(float x, float y) {
    __half2 t = __floats2half2_rn(x, y);
    return *reinterpret_cast<uint32_t*>(&t);
}
__device__ __forceinline__ void ldmx4(uint32_t* r, uint32_t addr) {
    asm volatile("ldmatrix.sync.aligned.m8n8.x4.shared.b16 {%0,%1,%2,%3}, [%4];"
                 : "=r"(r[0]), "=r"(r[1]), "=r"(r[2]), "=r"(r[3]) : "r"(addr));
}
__device__ __forceinline__ void mma16816(float* d, const uint32_t* a, uint32_t b0, uint32_t b1) {
    asm volatile("mma.sync.aligned.m16n8k16.row.col.f32.f16.f16.f32 "
                 "{%0,%1,%2,%3}, {%4,%5,%6,%7}, {%8,%9}, {%0,%1,%2,%3};"
                 : "+f"(d[0]), "+f"(d[1]), "+f"(d[2]), "+f"(d[3])
                 : "r"(a[0]), "r"(a[1]), "r"(a[2]), "r"(a[3]), "r"(b0), "r"(b1));
}
__device__ __forceinline__ void sts64(uint32_t a, uint32_t x, uint32_t y) {
    asm volatile("st.shared.v2.b32 [%0], {%1,%2};" :: "r"(a), "r"(x), "r"(y) : "memory");
}
__device__ __forceinline__ void stsf2(uint32_t a, float x, float y) {
    asm volatile("st.shared.v2.f32 [%0], {%1,%2};" :: "r"(a), "f"(x), "f"(y) : "memory");
}
__device__ __forceinline__ void cpasync16(uint32_t dst, const void* src) {
    asm volatile("cp.async.cg.shared.global [%0], [%1], 16;" :: "r"(dst), "l"(src) : "memory");
}
__device__ __forceinline__ void cp_commit() { asm volatile("cp.async.commit_group;" ::: "memory"); }
__device__ __forceinline__ void cp_wait1() { asm volatile("cp.async.wait_group 1;" ::: "memory"); }
__device__ __forceinline__ void cp_wait0() { asm volatile("cp.async.wait_group 0;" ::: "memory"); }
__device__ __forceinline__ void atomicMaxFloat(float* addr, float val) {
    if (val >= 0.0f) atomicMax((int*)addr, __float_as_int(val));
    else             atomicMin((unsigned int*)addr, __float_as_uint(val));
}

// ---------------- prep: split weights into fp16 hi/lo, [n][kk] ----------------
__global__ void prep_weights(const float* __restrict__ W1, const float* __restrict__ W2) {
    int idx = blockIdx.x * blockDim.x + threadIdx.x;
    if (idx >= C_ * E_ * KW_) return;
    int k = idx % KW_;
    int e = (idx / KW_) % E_;
    int c = idx / (KW_ * E_);
    int kk = k * E_ + e;
    float w1 = W1[idx];
    __half h1 = __float2half_rn(w1);
    g_Bhi[(size_t)c * KKd + kk] = h1;
    g_Blo[(size_t)c * KKd + kk] = __float2half_rn(w1 - __half2float(h1));
    float w2 = W2[idx];
    __half h2 = __float2half_rn(w2);
    g_Bhi[(size_t)(C_ + c) * KKd + kk] = h2;
    g_Blo[(size_t)(C_ + c) * KKd + kk] = __float2half_rn(w2 - __half2float(h2));
}

__global__ void init_out(float* out) {
    int i = blockIdx.x * blockDim.x + threadIdx.x;
    if (i < B_ * C_) out[i] = -INFINITY;
}

// ---------------- main fused GEMM + gate + max ----------------
__global__ __launch_bounds__(NTH, 1)
void gemm_gate_max(const float* __restrict__ Z,
                   const float* __restrict__ b1,
                   const float* __restrict__ b2,
                   float* __restrict__ out) {
    extern __shared__ char smem[];
    const uint32_t sb = smem_u32(smem);
    const int tid  = threadIdx.x;
    const int wid  = tid >> 5;
    const int lane = tid & 31;
    const int wm   = wid & 1;        // M group (0..1), 64 rows
    const int wn   = wid >> 1;       // N group (0..3), 64 cols
    const int m_base = blockIdx.x * MT;

    const uint32_t fragBase = (uint32_t)((lane % 16) * PITCH + (lane / 16) * 16);
    const uint32_t wmOff = (uint32_t)(wm * 64 * PITCH);
    const uint32_t wnOff = (uint32_t)(wn * 64 * PITCH);

    // ---- A gmem/smem mapping: 4 float4 per thread per chunk ----
    const float* aSrc[4];
    uint32_t     aDst[4];
    {
#pragma unroll
        for (int q = 0; q < 4; q++) {
            int i   = tid + q * 256;       // 0..1023
            int row = i >> 3;              // 0..127
            int kw  = (i & 7) * 4;         // float index 0..28
            aSrc[q] = Z + (size_t)(m_base + row) * KKd + kw;
            aDst[q] = (uint32_t)(row * PITCH + kw * 2);
        }
    }
    // ---- B cp.async mapping: 4 granules (16B) per thread per (hi|lo) ----
    int      bN[4];
    uint32_t bDst[4];
    int      bKo[4];
    {
#pragma unroll
        for (int q = 0; q < 4; q++) {
            int g  = tid + q * 256;        // 0..1023
            bN[q]  = g >> 2;               // n: 0..255
            bKo[q] = (g & 3) * 8;          // fp16 offset in row
            bDst[q] = (uint32_t)(bN[q] * PITCH + bKo[q] * 2);
        }
    }

    float acc[4][8][4];
#pragma unroll
    for (int mi = 0; mi < 4; mi++)
#pragma unroll
        for (int ni = 0; ni < 8; ni++)
#pragma unroll
            for (int q = 0; q < 4; q++) acc[mi][ni][q] = 0.0f;

    float4 pA[4];

    // ---- prologue: chunk 0 ----
#pragma unroll
    for (int q = 0; q < 4; q++) pA[q] = *(const float4*)(aSrc[q]);
#pragma unroll
    for (int q = 0; q < 4; q++) {
        cpasync16(sb + SM_BH + bDst[q], g_Bhi + (size_t)bN[q] * KKd + bKo[q]);
        cpasync16(sb + SM_BL + bDst[q], g_Blo + (size_t)bN[q] * KKd + bKo[q]);
    }
    cp_commit();
#pragma unroll
    for (int q = 0; q < 4; q++) {
        float4 v = pA[q];
        sts64(sb + SM_A + aDst[q], pack_h2(v.x, v.y), pack_h2(v.z, v.w));
    }
#pragma unroll
    for (int q = 0; q < 4; q++) pA[q] = *(const float4*)(aSrc[q] + KC);

    for (int j = 0; j < NCHUNK; ++j) {
        const uint32_t cur = j & 1;
        const uint32_t nxt = cur ^ 1;

        __syncthreads();   // chunk j-1 consumed -> safe to overwrite stage nxt

        if (j + 1 < NCHUNK) {
            const int ke = (j + 1) * KC;
#pragma unroll
            for (int q = 0; q < 4; q++) {
                cpasync16(sb + SM_BH + nxt * B_STG + bDst[q], g_Bhi + (size_t)bN[q] * KKd + ke + bKo[q]);
                cpasync16(sb + SM_BL + nxt * B_STG + bDst[q], g_Blo + (size_t)bN[q] * KKd + ke + bKo[q]);
            }
            cp_commit();
#pragma unroll
            for (int q = 0; q < 4; q++) {
                float4 v = pA[q];
                sts64(sb + SM_A + nxt * A_STG + aDst[q], pack_h2(v.x, v.y), pack_h2(v.z, v.w));
            }
            cp_wait1();
        } else {
            cp_wait0();
        }
        __syncthreads();   // stage cur fully visible

        if (j + 2 < NCHUNK) {
#pragma unroll
            for (int q = 0; q < 4; q++) pA[q] = *(const float4*)(aSrc[q] + (j + 2) * KC);
        }

        // ---- compute chunk j: 2 k16 slices x 2 precision passes ----
        const uint32_t sA  = sb + SM_A  + cur * A_STG;
        const uint32_t sBh = sb + SM_BH + cur * B_STG;
        const uint32_t sBl = sb + SM_BL + cur * B_STG;

#pragma unroll
        for (int ks = 0; ks < 2; ks++) {
            const uint32_t ko = ks * 32;   // byte offset for k16 slice
            uint32_t af[4][4], bh[4][4], bl[4][4];
#pragma unroll
            for (int mi = 0; mi < 4; mi++)
                ldmx4(af[mi], sA + wmOff + mi * (16 * PITCH) + ko + fragBase);
#pragma unroll
            for (int n2 = 0; n2 < 4; n2++)
                ldmx4(bh[n2], sBh + wnOff + n2 * (16 * PITCH) + ko + fragBase);
#pragma unroll
            for (int n2 = 0; n2 < 4; n2++)
                ldmx4(bl[n2], sBl + wnOff + n2 * (16 * PITCH) + ko + fragBase);
            // pass A*Bh
#pragma unroll
            for (int mi = 0; mi < 4; mi++)
#pragma unroll
                for (int ni = 0; ni < 8; ni++)
                    mma16816(acc[mi][ni], af[mi], bh[ni >> 1][(ni & 1)], bh[ni >> 1][(ni & 1) + 2]);
            // pass A*Bl
#pragma unroll
            for (int mi = 0; mi < 4; mi++)
#pragma unroll
                for (int ni = 0; ni < 8; ni++)
                    mma16816(acc[mi][ni], af[mi], bl[ni >> 1][(ni & 1)], bl[ni >> 1][(ni & 1) + 2]);
        }
    }

    // ---- epilogue: dump acc to smem tile [128][EPITCH] ----
    __syncthreads();
    {
        const int laneR = lane >> 2;
        const int laneC = (lane & 3) * 2;
#pragma unroll
        for (int mi = 0; mi < 4; mi++) {
#pragma unroll
            for (int ni = 0; ni < 8; ni++) {
                int r = wm * 64 + mi * 16 + laneR;
                int c = wn * 64 + ni * 8 + laneC;
                uint32_t a0 = sb + (uint32_t)(r * (EPITCH * 4) + c * 4);
                stsf2(a0,                     acc[mi][ni][0], acc[mi][ni][1]);
                stsf2(a0 + 8 * (EPITCH * 4),  acc[mi][ni][2], acc[mi][ni][3]);
            }
        }
    }
    __syncthreads();

    // ---- gate + max over the 128 rows ----
    {
        float* sE = (float*)smem;
        float* sP = sE + 128 * EPITCH;
        const int c   = tid & 127;
        const int seg = tid >> 7;
        const float bb1 = b1[c];
        const float bb2 = b2[c];
        float gm = -INFINITY;
        for (int m = seg * 64; m < seg * 64 + 64; ++m) {
            float v1 = sE[m * EPITCH + c] + bb1;
            float v2 = sE[m * EPITCH + 128 + c] + bb2;
            float g  = v1 / (1.0f + __expf(-v2));
            gm = fmaxf(gm, g);
        }
        sP[tid] = gm;
        __syncthreads();
        if (tid < 128) {
            float v = fmaxf(sP[tid], sP[tid + 128]);
            const int bidx = blockIdx.x >> 4;   // 16 CTAs per batch
            atomicMaxFloat(&out[bidx * C_ + c], v);
        }
    }
}

extern "C" void kernel_launch(void* const* d_in, const int* in_sizes, int n_in,
                              void* d_out, int out_size) {
    const float* z  = (const float*)d_in[0];
    const float* W1 = (const float*)d_in[1];
    const float* b1 = (const float*)d_in[2];
    const float* W2 = (const float*)d_in[3];
    const float* b2 = (const float*)d_in[4];
    float* out = (float*)d_out;
    (void)in_sizes; (void)n_in; (void)out_size;

    cudaFuncSetAttribute(gemm_gate_max, cudaFuncAttributeMaxDynamicSharedMemorySize, SMEMSZ);

    prep_weights<<<(C_ * E_ * KW_ + 255) / 256, 256>>>(W1, W2);
    init_out<<<(B_ * C_ + 255) / 256, 256>>>(out);
    gemm_gate_max<<<Mtot / MT, NTH, SMEMSZ>>>(z, b1, b2, out);
}

// round 5
// speedup vs baseline: 4.5578x; 1.5303x over previous
#include <cuda_runtime.h>
#include <cuda_fp16.h>
#include <math.h>
#include <stdint.h>

// ---------------- problem constants ----------------
#define B_   8
#define E_   8
#define C_   128
#define KW_  512
#define Mtot 16384          // B*L
#define KKd  4096           // KW*E
#define NNd  256            // 2*C

// ---------------- GEMM tiling ----------------
#define MT     128          // CTA M tile
#define KC     32           // K chunk (fp16 elems)
#define NCHUNK (KKd / KC)   // 128
#define NTH    256          // 8 warps: 2(M) x 4(N), warp tile 64x64

// smem pitches/strides (bytes)
#define PITCH   80          // 40 fp16 per row (32 data + 8 pad) -> conflict-free ldmatrix
#define A_STG   (128 * PITCH)        // 10240 per stage
#define B_STG   (256 * PITCH)        // 20480 per stage
#define SM_A    0
#define SM_B    (2 * A_STG)          // 20480
#define SM_PIPE (SM_B + 2 * B_STG)   // 61440
// epilogue overlay (floats): tile [128][258] + partials [256]
#define EPITCH  258
#define SMEMSZ  (((128 * EPITCH + 256) * 4 > SM_PIPE) ? (128 * EPITCH + 256) * 4 : SM_PIPE)

// fp16 weights, [n][kk] K-major; n<128 -> W1, n>=128 -> W2
__device__ __half g_Bh[(size_t)NNd * KKd];

// ---------------- helpers ----------------
__device__ __forceinline__ uint32_t smem_u32(const void* p) {
    uint32_t a;
    asm("{ .reg .u64 t; cvta.to.shared.u64 t, %1; cvt.u32.u64 %0, t; }" : "=r"(a) : "l"(p));
    return a;
}
__device__ __forceinline__ uint32_t pack_h2(float x, float y) {
    __half2 t = __floats2half2_rn(x, y);
    return *reinterpret_cast<uint32_t*>(&t);
}
__device__ __forceinline__ void ldmx4(uint32_t* r, uint32_t addr) {
    asm volatile("ldmatrix.sync.aligned.m8n8.x4.shared.b16 {%0,%1,%2,%3}, [%4];"
                 : "=r"(r[0]), "=r"(r[1]), "=r"(r[2]), "=r"(r[3]) : "r"(addr));
}
__device__ __forceinline__ void mma16816(float* d, const uint32_t* a, uint32_t b0, uint32_t b1) {
    asm volatile("mma.sync.aligned.m16n8k16.row.col.f32.f16.f16.f32 "
                 "{%0,%1,%2,%3}, {%4,%5,%6,%7}, {%8,%9}, {%0,%1,%2,%3};"
                 : "+f"(d[0]), "+f"(d[1]), "+f"(d[2]), "+f"(d[3])
                 : "r"(a[0]), "r"(a[1]), "r"(a[2]), "r"(a[3]), "r"(b0), "r"(b1));
}
__device__ __forceinline__ void sts64(uint32_t a, uint32_t x, uint32_t y) {
    asm volatile("st.shared.v2.b32 [%0], {%1,%2};" :: "r"(a), "r"(x), "r"(y) : "memory");
}
__device__ __forceinline__ void stsf2(uint32_t a, float x, float y) {
    asm volatile("st.shared.v2.f32 [%0], {%1,%2};" :: "r"(a), "f"(x), "f"(y) : "memory");
}
__device__ __forceinline__ void cpasync16(uint32_t dst, const void* src) {
    asm volatile("cp.async.cg.shared.global [%0], [%1], 16;" :: "r"(dst), "l"(src) : "memory");
}
__device__ __forceinline__ void cp_commit() { asm volatile("cp.async.commit_group;" ::: "memory"); }
__device__ __forceinline__ void cp_wait1() { asm volatile("cp.async.wait_group 1;" ::: "memory"); }
__device__ __forceinline__ void cp_wait0() { asm volatile("cp.async.wait_group 0;" ::: "memory"); }
__device__ __forceinline__ void atomicMaxFloat(float* addr, float val) {
    if (val >= 0.0f) atomicMax((int*)addr, __float_as_int(val));
    else             atomicMin((unsigned int*)addr, __float_as_uint(val));
}

// ---------------- prep: round weights to fp16, [n][kk] ----------------
__global__ void prep_weights(const float* __restrict__ W1, const float* __restrict__ W2) {
    int idx = blockIdx.x * blockDim.x + threadIdx.x;
    if (idx >= C_ * E_ * KW_) return;
    int k = idx % KW_;
    int e = (idx / KW_) % E_;
    int c = idx / (KW_ * E_);
    int kk = k * E_ + e;
    g_Bh[(size_t)c * KKd + kk]        = __float2half_rn(W1[idx]);
    g_Bh[(size_t)(C_ + c) * KKd + kk] = __float2half_rn(W2[idx]);
}

__global__ void init_out(float* out) {
    int i = blockIdx.x * blockDim.x + threadIdx.x;
    if (i < B_ * C_) out[i] = -INFINITY;
}

// ---------------- main fused GEMM + gate + max ----------------
__global__ __launch_bounds__(NTH, 1)
void gemm_gate_max(const float* __restrict__ Z,
                   const float* __restrict__ b1,
                   const float* __restrict__ b2,
                   float* __restrict__ out) {
    extern __shared__ char smem[];
    const uint32_t sb = smem_u32(smem);
    const int tid  = threadIdx.x;
    const int wid  = tid >> 5;
    const int lane = tid & 31;
    const int wm   = wid & 1;        // M group (0..1), 64 rows
    const int wn   = wid >> 1;       // N group (0..3), 64 cols
    const int m_base = blockIdx.x * MT;

    const uint32_t fragBase = (uint32_t)((lane % 16) * PITCH + (lane / 16) * 16);
    const uint32_t wmOff = (uint32_t)(wm * 64 * PITCH);
    const uint32_t wnOff = (uint32_t)(wn * 64 * PITCH);

    // ---- A gmem/smem mapping: 4 float4 per thread per chunk ----
    const float* aSrc[4];
    uint32_t     aDst[4];
    {
#pragma unroll
        for (int q = 0; q < 4; q++) {
            int i   = tid + q * 256;       // 0..1023
            int row = i >> 3;              // 0..127
            int kw  = (i & 7) * 4;         // float index 0..28
            aSrc[q] = Z + (size_t)(m_base + row) * KKd + kw;
            aDst[q] = (uint32_t)(row * PITCH + kw * 2);
        }
    }
    // ---- B cp.async mapping: 4 granules (16B) per thread ----
    int      bN[4];
    uint32_t bDst[4];
    int      bKo[4];
    {
#pragma unroll
        for (int q = 0; q < 4; q++) {
            int g  = tid + q * 256;        // 0..1023
            bN[q]  = g >> 2;               // n: 0..255
            bKo[q] = (g & 3) * 8;          // fp16 offset in row
            bDst[q] = (uint32_t)(bN[q] * PITCH + bKo[q] * 2);
        }
    }

    float acc[4][8][4];
#pragma unroll
    for (int mi = 0; mi < 4; mi++)
#pragma unroll
        for (int ni = 0; ni < 8; ni++)
#pragma unroll
            for (int q = 0; q < 4; q++) acc[mi][ni][q] = 0.0f;

    float4 pA[4];

    // ---- prologue: chunk 0 ----
#pragma unroll
    for (int q = 0; q < 4; q++) pA[q] = *(const float4*)(aSrc[q]);
#pragma unroll
    for (int q = 0; q < 4; q++)
        cpasync16(sb + SM_B + bDst[q], g_Bh + (size_t)bN[q] * KKd + bKo[q]);
    cp_commit();
#pragma unroll
    for (int q = 0; q < 4; q++) {
        float4 v = pA[q];
        sts64(sb + SM_A + aDst[q], pack_h2(v.x, v.y), pack_h2(v.z, v.w));
    }
#pragma unroll
    for (int q = 0; q < 4; q++) pA[q] = *(const float4*)(aSrc[q] + KC);

    for (int j = 0; j < NCHUNK; ++j) {
        const uint32_t cur = j & 1;
        const uint32_t nxt = cur ^ 1;

        __syncthreads();   // chunk j-1 consumed -> safe to overwrite stage nxt

        if (j + 1 < NCHUNK) {
            const int ke = (j + 1) * KC;
#pragma unroll
            for (int q = 0; q < 4; q++)
                cpasync16(sb + SM_B + nxt * B_STG + bDst[q], g_Bh + (size_t)bN[q] * KKd + ke + bKo[q]);
            cp_commit();
#pragma unroll
            for (int q = 0; q < 4; q++) {
                float4 v = pA[q];
                sts64(sb + SM_A + nxt * A_STG + aDst[q], pack_h2(v.x, v.y), pack_h2(v.z, v.w));
            }
            cp_wait1();
        } else {
            cp_wait0();
        }
        __syncthreads();   // stage cur fully visible

        if (j + 2 < NCHUNK) {
#pragma unroll
            for (int q = 0; q < 4; q++) pA[q] = *(const float4*)(aSrc[q] + (j + 2) * KC);
        }

        // ---- compute chunk j: 2 k16 slices, single fp16 pass ----
        const uint32_t sA = sb + SM_A + cur * A_STG;
        const uint32_t sB = sb + SM_B + cur * B_STG;

#pragma unroll
        for (int ks = 0; ks < 2; ks++) {
            const uint32_t ko = ks * 32;   // byte offset for k16 slice
            uint32_t af[4][4], bf[4][4];
#pragma unroll
            for (int mi = 0; mi < 4; mi++)
                ldmx4(af[mi], sA + wmOff + mi * (16 * PITCH) + ko + fragBase);
#pragma unroll
            for (int n2 = 0; n2 < 4; n2++)
                ldmx4(bf[n2], sB + wnOff + n2 * (16 * PITCH) + ko + fragBase);
#pragma unroll
            for (int mi = 0; mi < 4; mi++)
#pragma unroll
                for (int ni = 0; ni < 8; ni++)
                    mma16816(acc[mi][ni], af[mi], bf[ni >> 1][(ni & 1)], bf[ni >> 1][(ni & 1) + 2]);
        }
    }

    // ---- epilogue: dump acc to smem tile [128][EPITCH] ----
    __syncthreads();
    {
        const int laneR = lane >> 2;
        const int laneC = (lane & 3) * 2;
#pragma unroll
        for (int mi = 0; mi < 4; mi++) {
#pragma unroll
            for (int ni = 0; ni < 8; ni++) {
                int r = wm * 64 + mi * 16 + laneR;
                int c = wn * 64 + ni * 8 + laneC;
                uint32_t a0 = sb + (uint32_t)(r * (EPITCH * 4) + c * 4);
                stsf2(a0,                     acc[mi][ni][0], acc[mi][ni][1]);
                stsf2(a0 + 8 * (EPITCH * 4),  acc[mi][ni][2], acc[mi][ni][3]);
            }
        }
    }
    __syncthreads();

    // ---- gate + max over the 128 rows ----
    {
        float* sE = (float*)smem;
        float* sP = sE + 128 * EPITCH;
        const int c   = tid & 127;
        const int seg = tid >> 7;
        const float bb1 = b1[c];
        const float bb2 = b2[c];
        float gm = -INFINITY;
        for (int m = seg * 64; m < seg * 64 + 64; ++m) {
            float v1 = sE[m * EPITCH + c] + bb1;
            float v2 = sE[m * EPITCH + 128 + c] + bb2;
            float g  = v1 / (1.0f + __expf(-v2));
            gm = fmaxf(gm, g);
        }
        sP[tid] = gm;
        __syncthreads();
        if (tid < 128) {
            float v = fmaxf(sP[tid], sP[tid + 128]);
            const int bidx = blockIdx.x >> 4;   // 16 CTAs per batch
            atomicMaxFloat(&out[bidx * C_ + c], v);
        }
    }
}

extern "C" void kernel_launch(void* const* d_in, const int* in_sizes, int n_in,
                              void* d_out, int out_size) {
    const float* z  = (const float*)d_in[0];
    const float* W1 = (const float*)d_in[1];
    const float* b1 = (const float*)d_in[2];
    const float* W2 = (const float*)d_in[3];
    const float* b2 = (const float*)d_in[4];
    float* out = (float*)d_out;
    (void)in_sizes; (void)n_in; (void)out_size;

    cudaFuncSetAttribute(gemm_gate_max, cudaFuncAttributeMaxDynamicSharedMemorySize, SMEMSZ);

    prep_weights<<<(C_ * E_ * KW_ + 255) / 256, 256>>>(W1, W2);
    init_out<<<(B_ * C_ + 255) / 256, 256>>>(out);
    gemm_gate_max<<<Mtot / MT, NTH, SMEMSZ>>>(z, b1, b2, out);
}

// round 6
// speedup vs baseline: 5.0886x; 1.1165x over previous
#include <cuda_runtime.h>
#include <cuda_fp16.h>
#include <math.h>
#include <stdint.h>

// ---------------- problem constants ----------------
#define B_   8
#define E_   8
#define C_   128
#define KW_  512
#define Mtot 16384          // B*L
#define KKd  4096           // KW*E
#define NNd  256            // 2*C

// ---------------- GEMM tiling ----------------
#define MT     64           // CTA M tile
#define KC     32           // K chunk (fp16 elems)
#define NCHUNK (KKd / KC)   // 128
#define NTH    256          // 8 warps: 2(M) x 4(N), warp tile 32x64
#define NCTA   (Mtot / MT)  // 256

// smem (bytes)
#define PITCH   80          // 40 fp16 per row -> conflict-free ldmatrix
#define A_STG   (64 * PITCH)         // 5120 per stage
#define B_STG   (256 * PITCH)        // 20480 per stage
#define SM_A    0
#define SM_B    (2 * A_STG)          // 10240
#define SM_PIPE (SM_B + 2 * B_STG)   // 51200
// epilogue v2 tile overlay: [64][132] floats = 33792 B (fits inside pipe region)
#define VPITCH  132
#define SMEMSZ  SM_PIPE

// fp16 weights, [n][kk] K-major; n<128 -> W1, n>=128 -> W2
__device__ __half g_Bh[(size_t)NNd * KKd];

// ---------------- helpers ----------------
__device__ __forceinline__ uint32_t smem_u32(const void* p) {
    uint32_t a;
    asm("{ .reg .u64 t; cvta.to.shared.u64 t, %1; cvt.u32.u64 %0, t; }" : "=r"(a) : "l"(p));
    return a;
}
__device__ __forceinline__ uint32_t pack_h2(float x, float y) {
    __half2 t = __floats2half2_rn(x, y);
    return *reinterpret_cast<uint32_t*>(&t);
}
__device__ __forceinline__ void ldmx4(uint32_t* r, uint32_t addr) {
    asm volatile("ldmatrix.sync.aligned.m8n8.x4.shared.b16 {%0,%1,%2,%3}, [%4];"
                 : "=r"(r[0]), "=r"(r[1]), "=r"(r[2]), "=r"(r[3]) : "r"(addr));
}
__device__ __forceinline__ void mma16816(float* d, const uint32_t* a, uint32_t b0, uint32_t b1) {
    asm volatile("mma.sync.aligned.m16n8k16.row.col.f32.f16.f16.f32 "
                 "{%0,%1,%2,%3}, {%4,%5,%6,%7}, {%8,%9}, {%0,%1,%2,%3};"
                 : "+f"(d[0]), "+f"(d[1]), "+f"(d[2]), "+f"(d[3])
                 : "r"(a[0]), "r"(a[1]), "r"(a[2]), "r"(a[3]), "r"(b0), "r"(b1));
}
__device__ __forceinline__ void sts64(uint32_t a, uint32_t x, uint32_t y) {
    asm volatile("st.shared.v2.b32 [%0], {%1,%2};" :: "r"(a), "r"(x), "r"(y) : "memory");
}
__device__ __forceinline__ void stsf2(uint32_t a, float x, float y) {
    asm volatile("st.shared.v2.f32 [%0], {%1,%2};" :: "r"(a), "f"(x), "f"(y) : "memory");
}
__device__ __forceinline__ void cpasync16(uint32_t dst, const void* src) {
    asm volatile("cp.async.cg.shared.global [%0], [%1], 16;" :: "r"(dst), "l"(src) : "memory");
}
__device__ __forceinline__ void cp_commit() { asm volatile("cp.async.commit_group;" ::: "memory"); }
__device__ __forceinline__ void cp_wait1() { asm volatile("cp.async.wait_group 1;" ::: "memory"); }
__device__ __forceinline__ void cp_wait0() { asm volatile("cp.async.wait_group 0;" ::: "memory"); }
__device__ __forceinline__ void atomicMaxFloat(float* addr, float val) {
    if (val >= 0.0f) atomicMax((int*)addr, __float_as_int(val));
    else             atomicMin((unsigned int*)addr, __float_as_uint(val));
}

// ---------------- prep: weights -> fp16 [n][kk], coalesced; also init out ----------------
__global__ void prep_weights(const float* __restrict__ W1, const float* __restrict__ W2,
                             float* __restrict__ out) {
    int idx = blockIdx.x * blockDim.x + threadIdx.x;   // over C_*KW_ = 65536
    if (idx < B_ * C_) out[idx] = -INFINITY;
    if (idx >= C_ * KW_) return;
    int c = idx / KW_;
    int k = idx % KW_;
    // gather 8 e-values (stride KW_ floats), write 8 contiguous halves (16B)
    uint32_t p1[4], p2[4];
#pragma unroll
    for (int e2 = 0; e2 < 4; e2++) {
        float a0 = W1[((size_t)c * E_ + 2 * e2) * KW_ + k];
        float a1 = W1[((size_t)c * E_ + 2 * e2 + 1) * KW_ + k];
        p1[e2] = pack_h2(a0, a1);
        float b0 = W2[((size_t)c * E_ + 2 * e2) * KW_ + k];
        float b1v = W2[((size_t)c * E_ + 2 * e2 + 1) * KW_ + k];
        p2[e2] = pack_h2(b0, b1v);
    }
    *(uint4*)&g_Bh[(size_t)c * KKd + k * E_]          = make_uint4(p1[0], p1[1], p1[2], p1[3]);
    *(uint4*)&g_Bh[(size_t)(C_ + c) * KKd + k * E_]   = make_uint4(p2[0], p2[1], p2[2], p2[3]);
}

// ---------------- main fused GEMM + gate + max ----------------
__global__ __launch_bounds__(NTH, 2)
void gemm_gate_max(const float* __restrict__ Z,
                   const float* __restrict__ b1,
                   const float* __restrict__ b2,
                   float* __restrict__ out) {
    extern __shared__ char smem[];
    const uint32_t sb = smem_u32(smem);
    const int tid  = threadIdx.x;
    const int wid  = tid >> 5;
    const int lane = tid & 31;
    const int wm   = wid & 1;        // M group (0..1), 32 rows each
    const int wn   = wid >> 1;       // N group (0..3), 64 cols each
    const int m_base = blockIdx.x * MT;

    const uint32_t fragBase = (uint32_t)((lane % 16) * PITCH + (lane / 16) * 16);
    const uint32_t wmOff = (uint32_t)(wm * 32 * PITCH);
    const uint32_t wnOff = (uint32_t)(wn * 64 * PITCH);

    // ---- A gmem/smem mapping: 2 float4 per thread per chunk ----
    const float* aSrc[2];
    uint32_t     aDst[2];
#pragma unroll
    for (int q = 0; q < 2; q++) {
        int i   = tid + q * 256;       // 0..511
        int row = i >> 3;              // 0..63
        int kw  = (i & 7) * 4;         // float index 0..28
        aSrc[q] = Z + (size_t)(m_base + row) * KKd + kw;
        aDst[q] = (uint32_t)(row * PITCH + kw * 2);
    }
    // ---- B cp.async mapping: 4 granules (16B) per thread ----
    int      bN[4];
    uint32_t bDst[4];
    int      bKo[4];
#pragma unroll
    for (int q = 0; q < 4; q++) {
        int g  = tid + q * 256;        // 0..1023
        bN[q]  = g >> 2;               // n: 0..255
        bKo[q] = (g & 3) * 8;          // fp16 offset in row
        bDst[q] = (uint32_t)(bN[q] * PITCH + bKo[q] * 2);
    }

    float acc[2][8][4];
#pragma unroll
    for (int mi = 0; mi < 2; mi++)
#pragma unroll
        for (int ni = 0; ni < 8; ni++)
#pragma unroll
            for (int q = 0; q < 4; q++) acc[mi][ni][q] = 0.0f;

    float4 pA[2];

    // ---- prologue: chunk 0 ----
#pragma unroll
    for (int q = 0; q < 2; q++) pA[q] = *(const float4*)(aSrc[q]);
#pragma unroll
    for (int q = 0; q < 4; q++)
        cpasync16(sb + SM_B + bDst[q], g_Bh + (size_t)bN[q] * KKd + bKo[q]);
    cp_commit();
#pragma unroll
    for (int q = 0; q < 2; q++) {
        float4 v = pA[q];
        sts64(sb + SM_A + aDst[q], pack_h2(v.x, v.y), pack_h2(v.z, v.w));
    }
#pragma unroll
    for (int q = 0; q < 2; q++) pA[q] = *(const float4*)(aSrc[q] + KC);

    for (int j = 0; j < NCHUNK; ++j) {
        const uint32_t cur = j & 1;
        const uint32_t nxt = cur ^ 1;

        __syncthreads();   // chunk j-1 consumed -> safe to overwrite stage nxt

        if (j + 1 < NCHUNK) {
            const int ke = (j + 1) * KC;
#pragma unroll
            for (int q = 0; q < 4; q++)
                cpasync16(sb + SM_B + nxt * B_STG + bDst[q], g_Bh + (size_t)bN[q] * KKd + ke + bKo[q]);
            cp_commit();
#pragma unroll
            for (int q = 0; q < 2; q++) {
                float4 v = pA[q];
                sts64(sb + SM_A + nxt * A_STG + aDst[q], pack_h2(v.x, v.y), pack_h2(v.z, v.w));
            }
            cp_wait1();
        } else {
            cp_wait0();
        }
        __syncthreads();   // stage cur fully visible

        if (j + 2 < NCHUNK) {
#pragma unroll
            for (int q = 0; q < 2; q++) pA[q] = *(const float4*)(aSrc[q] + (j + 2) * KC);
        }

        // ---- compute chunk j: 2 k16 slices, single fp16 pass ----
        const uint32_t sA = sb + SM_A + cur * A_STG;
        const uint32_t sB = sb + SM_B + cur * B_STG;

#pragma unroll
        for (int ks = 0; ks < 2; ks++) {
            const uint32_t ko = ks * 32;
            uint32_t af[2][4], bf[4][4];
#pragma unroll
            for (int mi = 0; mi < 2; mi++)
                ldmx4(af[mi], sA + wmOff + mi * (16 * PITCH) + ko + fragBase);
#pragma unroll
            for (int n2 = 0; n2 < 4; n2++)
                ldmx4(bf[n2], sB + wnOff + n2 * (16 * PITCH) + ko + fragBase);
#pragma unroll
            for (int mi = 0; mi < 2; mi++)
#pragma unroll
                for (int ni = 0; ni < 8; ni++)
                    mma16816(acc[mi][ni], af[mi], bf[ni >> 1][(ni & 1)], bf[ni >> 1][(ni & 1) + 2]);
        }
    }

    // ---- epilogue ----
    __syncthreads();   // pipe done; reuse smem as v2 tile [64][VPITCH] floats

    const int laneR = lane >> 2;
    const int laneC = (lane & 3) * 2;

    if (wn >= 2) {
        // dump v2 half (global cols 128..255 -> tile cols 0..127)
#pragma unroll
        for (int mi = 0; mi < 2; mi++) {
#pragma unroll
            for (int ni = 0; ni < 8; ni++) {
                int r = wm * 32 + mi * 16 + laneR;
                int c = (wn - 2) * 64 + ni * 8 + laneC;
                uint32_t a0 = sb + (uint32_t)(r * (VPITCH * 4) + c * 4);
                stsf2(a0,                    acc[mi][ni][0], acc[mi][ni][1]);
                stsf2(a0 + 8 * (VPITCH * 4), acc[mi][ni][2], acc[mi][ni][3]);
            }
        }
    }
    __syncthreads();

    if (wn < 2) {
        const float* sV = (const float*)smem;
        const int bidx = blockIdx.x >> 5;   // 32 CTAs per batch
        float gm[8][2];
#pragma unroll
        for (int ni = 0; ni < 8; ni++) {
            const int c = wn * 64 + ni * 8 + laneC;
            const float bb1a = __ldg(&b1[c]),     bb1b = __ldg(&b1[c + 1]);
            const float bb2a = __ldg(&b2[c]),     bb2b = __ldg(&b2[c + 1]);
            float m0 = -INFINITY, m1 = -INFINITY;
#pragma unroll
            for (int mi = 0; mi < 2; mi++) {
                int r0 = wm * 32 + mi * 16 + laneR;
                float v2a0 = sV[r0 * VPITCH + c]           + bb2a;
                float v2b0 = sV[r0 * VPITCH + c + 1]       + bb2b;
                float v2a1 = sV[(r0 + 8) * VPITCH + c]     + bb2a;
                float v2b1 = sV[(r0 + 8) * VPITCH + c + 1] + bb2b;
                float g0 = (acc[mi][ni][0] + bb1a) / (1.0f + __expf(-v2a0));
                float g1 = (acc[mi][ni][1] + bb1b) / (1.0f + __expf(-v2b0));
                float g2 = (acc[mi][ni][2] + bb1a) / (1.0f + __expf(-v2a1));
                float g3 = (acc[mi][ni][3] + bb1b) / (1.0f + __expf(-v2b1));
                m0 = fmaxf(m0, fmaxf(g0, g2));
                m1 = fmaxf(m1, fmaxf(g1, g3));
            }
            gm[ni][0] = m0;
            gm[ni][1] = m1;
        }
        // reduce over laneR (rows) within warp
#pragma unroll
        for (int ni = 0; ni < 8; ni++) {
#pragma unroll
            for (int off = 4; off < 32; off <<= 1) {
                gm[ni][0] = fmaxf(gm[ni][0], __shfl_xor_sync(0xffffffffu, gm[ni][0], off));
                gm[ni][1] = fmaxf(gm[ni][1], __shfl_xor_sync(0xffffffffu, gm[ni][1], off));
            }
        }
        if (laneR == 0) {
#pragma unroll
            for (int ni = 0; ni < 8; ni++) {
                int c = wn * 64 + ni * 8 + laneC;
                atomicMaxFloat(&out[bidx * C_ + c],     gm[ni][0]);
                atomicMaxFloat(&out[bidx * C_ + c + 1], gm[ni][1]);
            }
        }
    }
}

extern "C" void kernel_launch(void* const* d_in, const int* in_sizes, int n_in,
                              void* d_out, int out_size) {
    const float* z  = (const float*)d_in[0];
    const float* W1 = (const float*)d_in[1];
    const float* b1 = (const float*)d_in[2];
    const float* W2 = (const float*)d_in[3];
    const float* b2 = (const float*)d_in[4];
    float* out = (float*)d_out;
    (void)in_sizes; (void)n_in; (void)out_size;

    cudaFuncSetAttribute(gemm_gate_max, cudaFuncAttributeMaxDynamicSharedMemorySize, SMEMSZ);

    prep_weights<<<(C_ * KW_ + 255) / 256, 256>>>(W1, W2, out);
    gemm_gate_max<<<NCTA, NTH, SMEMSZ>>>(z, b1, b2, out);
}